// round 7
// baseline (speedup 1.0000x reference)
#include <cuda_runtime.h>
#include <cuda_fp16.h>

// Problem constants (from reference)
#define K_GENES 20000
#define N_GO    5000
#define BATCH   4096
#define CAP     128            // per-column entry capacity (Poisson(16); max ~50)
#define JT      32             // columns per spmm block
#define BT      256            // batch elems per spmm block

// Scratch in device globals (allocation inside kernel_launch is forbidden)
__device__ __half g_xTh[(size_t)K_GENES * BATCH];  // x transposed, fp16: [gene][batch]
__device__ int    g_cnt[N_GO];
__device__ int    g_ei [(size_t)N_GO * CAP];       // gene index per entry
__device__ float  g_ev [(size_t)N_GO * CAP];       // weight*mask value per entry

// ---------------------------------------------------------------------------
// 1) zero per-column counters
__global__ void zero_cnt_kernel() {
    int t = blockIdx.x * blockDim.x + threadIdx.x;
    if (t < N_GO) g_cnt[t] = 0;
}

// ---------------------------------------------------------------------------
// 2) scan mask (99.92% zero -> pure float4 stream, evict-first), append entries
__global__ void build_entries_kernel(const float* __restrict__ w,
                                     const float* __restrict__ m) {
    const float4* m4 = (const float4*)m;
    const long total4 = (long)K_GENES * N_GO / 4;
    long stride = (long)gridDim.x * blockDim.x;
    for (long idx = (long)blockIdx.x * blockDim.x + threadIdx.x; idx < total4; idx += stride) {
        float4 mv = __ldcs(m4 + idx);
        if (mv.x != 0.f || mv.y != 0.f || mv.z != 0.f || mv.w != 0.f) {
            float lane[4] = {mv.x, mv.y, mv.z, mv.w};
            long base = idx * 4;
            #pragma unroll
            for (int c = 0; c < 4; c++) {
                if (lane[c] != 0.f) {
                    long lin = base + c;
                    int i = (int)(lin / N_GO);
                    int j = (int)(lin - (long)i * N_GO);
                    float wv = __ldg(w + lin) * lane[c];
                    int pos = atomicAdd(&g_cnt[j], 1);
                    if (pos < CAP) {
                        g_ei[(size_t)j * CAP + pos] = i;
                        g_ev[(size_t)j * CAP + pos] = wv;
                    }
                }
            }
        }
    }
}

// ---------------------------------------------------------------------------
// 2b) sort each column's entry list by gene id ONCE (deterministic FP order).
__global__ void sort_entries_kernel() {
    __shared__ int   s_i[8][CAP];
    __shared__ float s_v[8][CAP];
    int w    = threadIdx.x >> 5;
    int lane = threadIdx.x & 31;
    int j    = blockIdx.x * 8 + w;
    if (j >= N_GO) return;
    int n = min(g_cnt[j], CAP);

    for (int e = lane; e < n; e += 32) {
        s_i[w][e] = g_ei[(size_t)j * CAP + e];
        s_v[w][e] = g_ev[(size_t)j * CAP + e];
    }
    __syncwarp();
    for (int p = 0; p < n; p++) {
        for (int k = (p & 1) + 2 * lane; k + 1 < n; k += 64) {
            if (s_i[w][k] > s_i[w][k + 1]) {
                int   ti = s_i[w][k]; s_i[w][k] = s_i[w][k + 1]; s_i[w][k + 1] = ti;
                float tv = s_v[w][k]; s_v[w][k] = s_v[w][k + 1]; s_v[w][k + 1] = tv;
            }
        }
        __syncwarp();
    }
    for (int e = lane; e < n; e += 32) {
        g_ei[(size_t)j * CAP + e] = s_i[w][e];
        g_ev[(size_t)j * CAP + e] = s_v[w][e];
    }
}

// ---------------------------------------------------------------------------
// 3) transpose x [4096, 20000] fp32 -> g_xTh [20000, 4096] fp16.
//    Full-batch version (ran at the LTS cap: 6307 GB/s).
//    Tile 64 genes x 64 batch; float4 LDG.128 evict-first reads, uint4 writes.
__global__ void transpose_x_h_kernel(const float* __restrict__ in) {
    __shared__ float tile[64][65];
    int t  = threadIdx.x;
    int c0 = blockIdx.x * 64;                // gene base
    int r0 = blockIdx.y * 64;                // batch base

    int fx = t & 15;
    int rr = t >> 4;
    bool cok = (c0 + 4 * fx) < K_GENES;
    #pragma unroll
    for (int p = 0; p < 4; p++) {
        int r = rr + 16 * p;
        if (cok) {
            float4 v = __ldcs((const float4*)(in + (size_t)(r0 + r) * K_GENES + c0 + 4 * fx));
            tile[r][4 * fx + 0] = v.x;
            tile[r][4 * fx + 1] = v.y;
            tile[r][4 * fx + 2] = v.z;
            tile[r][4 * fx + 3] = v.w;
        }
    }
    __syncthreads();

    int u  = t & 7;
    int gl = t >> 3;
    #pragma unroll
    for (int p = 0; p < 2; p++) {
        int g = gl + 32 * p;
        if (c0 + g < K_GENES) {
            __half2 h0 = __floats2half2_rn(tile[8 * u + 0][g], tile[8 * u + 1][g]);
            __half2 h1 = __floats2half2_rn(tile[8 * u + 2][g], tile[8 * u + 3][g]);
            __half2 h2 = __floats2half2_rn(tile[8 * u + 4][g], tile[8 * u + 5][g]);
            __half2 h3 = __floats2half2_rn(tile[8 * u + 6][g], tile[8 * u + 7][g]);
            uint4 o;
            o.x = *(unsigned*)&h0; o.y = *(unsigned*)&h1;
            o.z = *(unsigned*)&h2; o.w = *(unsigned*)&h3;
            *(uint4*)&g_xTh[(size_t)(c0 + g) * BATCH + r0 + 8 * u] = o;
        }
    }
}

// ---------------------------------------------------------------------------
// 4) fused sparse accumulation + direct output write, SOFTWARE-PIPELINED.
//    Block = (32 columns, 256 batch). Warp w owns 4 columns x 256 batch.
//    Entry loop keeps 2 LDG.128 in flight (lists padded with 2 duplicate
//    tail entries so the prefetch needs no branches).
__global__ void spmm_fused_kernel(float* __restrict__ out) {
    __shared__ int   s_ei[8][CAP + 2];
    __shared__ float s_ev[8][CAP + 2];
    __shared__ float s_out[BT][JT + 1];

    int w     = threadIdx.x >> 5;
    int lane  = threadIdx.x & 31;
    int b0    = blockIdx.y * BT;
    int jbase = blockIdx.x * JT + w * 4;

    #pragma unroll
    for (int cc = 0; cc < 4; cc++) {
        int j = jbase + cc;
        int n = 0;
        if (j < N_GO) n = min(g_cnt[j], CAP);

        for (int e = lane; e < n; e += 32) {
            s_ei[w][e] = g_ei[(size_t)j * CAP + e];
            s_ev[w][e] = g_ev[(size_t)j * CAP + e];
        }
        __syncwarp();
        if (lane < 2 && n > 0) {            // pad 2 tail slots (safe addresses)
            s_ei[w][n + lane] = s_ei[w][n - 1];
            s_ev[w][n + lane] = 0.f;
        }
        __syncwarp();

        float acc[8];
        #pragma unroll
        for (int q = 0; q < 8; q++) acc[q] = 0.f;

        const __half* xb = g_xTh + b0 + lane * 8;
        if (n > 0) {
            uint4 u0 = __ldg((const uint4*)(xb + (size_t)s_ei[w][0] * BATCH));
            uint4 u1 = __ldg((const uint4*)(xb + (size_t)s_ei[w][1] * BATCH));
            for (int e = 0; e < n; e++) {
                uint4 cur = u0;
                u0 = u1;
                u1 = __ldg((const uint4*)(xb + (size_t)s_ei[w][e + 2] * BATCH));
                float v = s_ev[w][e];
                float2 f0 = __half22float2(*(__half2*)&cur.x);
                float2 f1 = __half22float2(*(__half2*)&cur.y);
                float2 f2 = __half22float2(*(__half2*)&cur.z);
                float2 f3 = __half22float2(*(__half2*)&cur.w);
                acc[0] = fmaf(f0.x, v, acc[0]);
                acc[1] = fmaf(f0.y, v, acc[1]);
                acc[2] = fmaf(f1.x, v, acc[2]);
                acc[3] = fmaf(f1.y, v, acc[3]);
                acc[4] = fmaf(f2.x, v, acc[4]);
                acc[5] = fmaf(f2.y, v, acc[5]);
                acc[6] = fmaf(f3.x, v, acc[6]);
                acc[7] = fmaf(f3.y, v, acc[7]);
            }
        }
        __syncwarp();

        #pragma unroll
        for (int q = 0; q < 8; q++) {
            s_out[lane * 8 + q][w * 4 + cc] = acc[q];
        }
    }
    __syncthreads();

    // coalesced evict-first write: 128B per row segment out[b, j0..j0+31]
    int col = threadIdx.x & 31;
    int j   = blockIdx.x * JT + col;
    if (j < N_GO) {
        #pragma unroll 4
        for (int r = threadIdx.x >> 5; r < BT; r += 8) {
            __stcs(&out[(size_t)(b0 + r) * N_GO + j], s_out[r][col]);
        }
    }
}

// ---------------------------------------------------------------------------
extern "C" void kernel_launch(void* const* d_in, const int* in_sizes, int n_in,
                              void* d_out, int out_size) {
    const float* x = (const float*)d_in[0];   // [4096, 20000]
    const float* w = (const float*)d_in[1];   // [20000, 5000]
    const float* m = (const float*)d_in[2];   // [20000, 5000]
    float* out = (float*)d_out;               // [4096, 5000]

    zero_cnt_kernel<<<(N_GO + 255) / 256, 256>>>();
    build_entries_kernel<<<4736, 256>>>(w, m);
    sort_entries_kernel<<<(N_GO + 7) / 8, 256>>>();

    transpose_x_h_kernel<<<dim3((K_GENES + 63) / 64, BATCH / 64), 256>>>(x);

    spmm_fused_kernel<<<dim3((N_GO + JT - 1) / JT, BATCH / BT), 256>>>(out);
}

// round 8
// speedup vs baseline: 1.0184x; 1.0184x over previous
#include <cuda_runtime.h>
#include <cuda_fp16.h>

// Problem constants (from reference)
#define K_GENES 20000
#define N_GO    5000
#define BATCH   4096
#define CAP     128            // per-column entry capacity (Poisson(16); max ~50)
#define JT      32             // columns per spmm block
#define BT      256            // batch elems per spmm block
#define CHUNK   1024           // batch rows per pipeline chunk (staging = 41MB, L2-resident)

// Scratch in device globals (allocation inside kernel_launch is forbidden)
// Staging buffer reused across chunks: [gene][CHUNK] fp16 -> stays in L2.
__device__ __half g_stage[(size_t)K_GENES * CHUNK];
__device__ int    g_cnt[N_GO];
__device__ int    g_ei [(size_t)N_GO * (CAP + 2)]; // gene index per entry (padded)
__device__ float  g_ev [(size_t)N_GO * (CAP + 2)]; // weight*mask value per entry (padded)

// ---------------------------------------------------------------------------
// 1) zero per-column counters
__global__ void zero_cnt_kernel() {
    int t = blockIdx.x * blockDim.x + threadIdx.x;
    if (t < N_GO) g_cnt[t] = 0;
}

// ---------------------------------------------------------------------------
// 2) scan mask (99.92% zero -> pure float4 stream, evict-first), append entries
__global__ void build_entries_kernel(const float* __restrict__ w,
                                     const float* __restrict__ m) {
    const float4* m4 = (const float4*)m;
    const long total4 = (long)K_GENES * N_GO / 4;
    long stride = (long)gridDim.x * blockDim.x;
    for (long idx = (long)blockIdx.x * blockDim.x + threadIdx.x; idx < total4; idx += stride) {
        float4 mv = __ldcs(m4 + idx);
        if (mv.x != 0.f || mv.y != 0.f || mv.z != 0.f || mv.w != 0.f) {
            float lane[4] = {mv.x, mv.y, mv.z, mv.w};
            long base = idx * 4;
            #pragma unroll
            for (int c = 0; c < 4; c++) {
                if (lane[c] != 0.f) {
                    long lin = base + c;
                    int i = (int)(lin / N_GO);
                    int j = (int)(lin - (long)i * N_GO);
                    float wv = __ldg(w + lin) * lane[c];
                    int pos = atomicAdd(&g_cnt[j], 1);
                    if (pos < CAP) {
                        g_ei[(size_t)j * (CAP + 2) + pos] = i;
                        g_ev[(size_t)j * (CAP + 2) + pos] = wv;
                    }
                }
            }
        }
    }
}

// ---------------------------------------------------------------------------
// 2b) sort each column's entry list by gene id ONCE (deterministic FP order),
//     and write 2 duplicate tail entries so spmm's prefetch needs no branches.
__global__ void sort_entries_kernel() {
    __shared__ int   s_i[8][CAP];
    __shared__ float s_v[8][CAP];
    int w    = threadIdx.x >> 5;
    int lane = threadIdx.x & 31;
    int j    = blockIdx.x * 8 + w;
    if (j >= N_GO) return;
    int n = min(g_cnt[j], CAP);
    size_t base = (size_t)j * (CAP + 2);

    for (int e = lane; e < n; e += 32) {
        s_i[w][e] = g_ei[base + e];
        s_v[w][e] = g_ev[base + e];
    }
    __syncwarp();
    for (int p = 0; p < n; p++) {
        for (int k = (p & 1) + 2 * lane; k + 1 < n; k += 64) {
            if (s_i[w][k] > s_i[w][k + 1]) {
                int   ti = s_i[w][k]; s_i[w][k] = s_i[w][k + 1]; s_i[w][k + 1] = ti;
                float tv = s_v[w][k]; s_v[w][k] = s_v[w][k + 1]; s_v[w][k + 1] = tv;
            }
        }
        __syncwarp();
    }
    for (int e = lane; e < n; e += 32) {
        g_ei[base + e] = s_i[w][e];
        g_ev[base + e] = s_v[w][e];
    }
    if (lane < 2) {                       // padded tail (safe addr, zero weight)
        int last = (n > 0) ? s_i[w][n - 1] : 0;
        g_ei[base + n + lane] = last;
        g_ev[base + n + lane] = 0.f;
    }
}

// ---------------------------------------------------------------------------
// 3) transpose one batch chunk of x -> g_stage [gene][CHUNK] fp16.
//    Tile 64 genes x 64 batch; float4 LDG.128 evict-first reads (x is
//    stream-once), uint4 STG.128 staging writes (normal policy: L2-resident).
__global__ void transpose_chunk_kernel(const float* __restrict__ in, int chunk) {
    __shared__ float tile[64][65];
    int t  = threadIdx.x;
    int c0 = blockIdx.x * 64;                // gene base
    int rl = blockIdx.y * 64;                // batch base within chunk
    int r0 = chunk * CHUNK + rl;             // global batch base

    int fx = t & 15;
    int rr = t >> 4;
    bool cok = (c0 + 4 * fx) < K_GENES;
    #pragma unroll
    for (int p = 0; p < 4; p++) {
        int r = rr + 16 * p;
        if (cok) {
            float4 v = __ldcs((const float4*)(in + (size_t)(r0 + r) * K_GENES + c0 + 4 * fx));
            tile[r][4 * fx + 0] = v.x;
            tile[r][4 * fx + 1] = v.y;
            tile[r][4 * fx + 2] = v.z;
            tile[r][4 * fx + 3] = v.w;
        }
    }
    __syncthreads();

    int u  = t & 7;
    int gl = t >> 3;
    #pragma unroll
    for (int p = 0; p < 2; p++) {
        int g = gl + 32 * p;
        if (c0 + g < K_GENES) {
            __half2 h0 = __floats2half2_rn(tile[8 * u + 0][g], tile[8 * u + 1][g]);
            __half2 h1 = __floats2half2_rn(tile[8 * u + 2][g], tile[8 * u + 3][g]);
            __half2 h2 = __floats2half2_rn(tile[8 * u + 4][g], tile[8 * u + 5][g]);
            __half2 h3 = __floats2half2_rn(tile[8 * u + 6][g], tile[8 * u + 7][g]);
            uint4 o;
            o.x = *(unsigned*)&h0; o.y = *(unsigned*)&h1;
            o.z = *(unsigned*)&h2; o.w = *(unsigned*)&h3;
            *(uint4*)&g_stage[(size_t)(c0 + g) * CHUNK + rl + 8 * u] = o;
        }
    }
}

// ---------------------------------------------------------------------------
// 4) fused sparse accumulation over one chunk, reading L2-resident staging.
//    SOFTWARE-PIPELINED depth 2: every iteration keeps 2 independent LDG.128
//    in flight (lists pre-padded with 2 duplicate zero-weight tail entries).
//    Output written evict-first (stream-once).
__global__ void spmm_chunk_kernel(float* __restrict__ out, int chunk) {
    __shared__ int   s_ei[8][CAP + 2];
    __shared__ float s_ev[8][CAP + 2];
    __shared__ float s_out[BT][JT + 1];

    int w     = threadIdx.x >> 5;
    int lane  = threadIdx.x & 31;
    int bl    = blockIdx.y * BT;             // batch base within chunk
    int b0    = chunk * CHUNK + bl;          // global batch base
    int jbase = blockIdx.x * JT + w * 4;

    #pragma unroll
    for (int cc = 0; cc < 4; cc++) {
        int j = jbase + cc;
        int n = 0;
        if (j < N_GO) n = min(g_cnt[j], CAP);
        size_t lbase = (size_t)j * (CAP + 2);

        for (int e = lane; e < n + 2 && j < N_GO; e += 32) {
            s_ei[w][e] = g_ei[lbase + e];
            s_ev[w][e] = g_ev[lbase + e];
        }
        __syncwarp();

        float acc[8];
        #pragma unroll
        for (int q = 0; q < 8; q++) acc[q] = 0.f;

        const __half* xb = g_stage + bl + lane * 8;
        if (n > 0) {
            uint4 u0 = __ldg((const uint4*)(xb + (size_t)s_ei[w][0] * CHUNK));
            uint4 u1 = __ldg((const uint4*)(xb + (size_t)s_ei[w][1] * CHUNK));
            for (int e = 0; e < n; e++) {
                uint4 cur = u0;
                u0 = u1;
                u1 = __ldg((const uint4*)(xb + (size_t)s_ei[w][e + 2] * CHUNK));
                float v = s_ev[w][e];
                float2 f0 = __half22float2(*(__half2*)&cur.x);
                float2 f1 = __half22float2(*(__half2*)&cur.y);
                float2 f2 = __half22float2(*(__half2*)&cur.z);
                float2 f3 = __half22float2(*(__half2*)&cur.w);
                acc[0] = fmaf(f0.x, v, acc[0]);
                acc[1] = fmaf(f0.y, v, acc[1]);
                acc[2] = fmaf(f1.x, v, acc[2]);
                acc[3] = fmaf(f1.y, v, acc[3]);
                acc[4] = fmaf(f2.x, v, acc[4]);
                acc[5] = fmaf(f2.y, v, acc[5]);
                acc[6] = fmaf(f3.x, v, acc[6]);
                acc[7] = fmaf(f3.y, v, acc[7]);
            }
        }
        __syncwarp();

        #pragma unroll
        for (int q = 0; q < 8; q++) {
            s_out[lane * 8 + q][w * 4 + cc] = acc[q];
        }
    }
    __syncthreads();

    // coalesced evict-first write: 128B per row segment out[b, j0..j0+31]
    int col = threadIdx.x & 31;
    int j   = blockIdx.x * JT + col;
    if (j < N_GO) {
        #pragma unroll 4
        for (int r = threadIdx.x >> 5; r < BT; r += 8) {
            __stcs(&out[(size_t)(b0 + r) * N_GO + j], s_out[r][col]);
        }
    }
}

// ---------------------------------------------------------------------------
extern "C" void kernel_launch(void* const* d_in, const int* in_sizes, int n_in,
                              void* d_out, int out_size) {
    const float* x = (const float*)d_in[0];   // [4096, 20000]
    const float* w = (const float*)d_in[1];   // [20000, 5000]
    const float* m = (const float*)d_in[2];   // [20000, 5000]
    float* out = (float*)d_out;               // [4096, 5000]

    zero_cnt_kernel<<<(N_GO + 255) / 256, 256>>>();
    build_entries_kernel<<<4736, 256>>>(w, m);
    sort_entries_kernel<<<(N_GO + 7) / 8, 256>>>();

    dim3 tgrid((K_GENES + 63) / 64, CHUNK / 64);
    dim3 sgrid((N_GO + JT - 1) / JT, CHUNK / BT);
    for (int c = 0; c < BATCH / CHUNK; c++) {
        transpose_chunk_kernel<<<tgrid, 256>>>(x, c);
        spmm_chunk_kernel<<<sgrid, 256>>>(out, c);
    }
}